// round 14
// baseline (speedup 1.0000x reference)
#include <cuda_runtime.h>
#include <cstdint>

// Problem constants
#define H_   128
#define W_   256
#define C_   128
#define B_   8
#define HW_  (H_ * W_)
#define CHW_ (C_ * HW_)

// Tiling
#define TH   8              // output rows per block
#define TW   32             // output cols per block
#define NDY  9              // dy values (threadIdx.y)
#define CC   8              // channels per chunk
#define NC   (C_ / CC)      // 16 chunks
#define X1W  36             // x1 tile cols: 32 + 4 (need a[8] boundary; 16B granular)
#define X2H  (TH + 8)       // 16 x2 rows in tile
#define X2W  52             // 48 data cols + 4 pad (52 mod 32 = 20 -> conflict-free rows)
#define S1   (CC * TH * X1W)         // x1 tile floats  = 2304
#define S2   (CC * X2H * X2W)        // x2 tile floats  = 6656
#define BUFF (S1 + S2)               // 8960 floats per buffer
#define SMEM_BYTES (2 * BUFF * 4)    // 71680 B (double buffered) -> 2 CTAs/SM
#define NTHREADS 288

typedef unsigned long long ull;

__device__ __forceinline__ ull pk2(float lo, float hi) {
    ull r;
    asm("mov.b64 %0, {%1, %2};"
        : "=l"(r) : "r"(__float_as_uint(lo)), "r"(__float_as_uint(hi)));
    return r;
}
__device__ __forceinline__ void fma2(ull& d, ull a, ull b) {
    asm("fma.rn.f32x2 %0, %1, %2, %0;" : "+l"(d) : "l"(a), "l"(b));
}
__device__ __forceinline__ void upk2(ull v, float& lo, float& hi) {
    unsigned l, h;
    asm("mov.b64 {%0, %1}, %2;" : "=r"(l), "=r"(h) : "l"(v));
    lo = __uint_as_float(l); hi = __uint_as_float(h);
}
__device__ __forceinline__ float loF(ull v) { return __uint_as_float((unsigned)v); }
__device__ __forceinline__ float hiF(ull v) { return __uint_as_float((unsigned)(v >> 32)); }
__device__ __forceinline__ void cp16(unsigned sdst, const float* g, bool valid) {
    int sz = valid ? 16 : 0;   // src-size 0 => zero-fill 16B
    asm volatile("cp.async.cg.shared.global [%0], [%1], 16, %2;"
                 :: "r"(sdst), "l"(g), "r"(sz));
}
__device__ __forceinline__ float leaky(float v) {
    return (v > 0.0f) ? v : 0.1f * v;
}

__global__ void __launch_bounds__(NTHREADS, 2)
corr_kernel(const float* __restrict__ x1, const float* __restrict__ x2,
            float* __restrict__ out)
{
    extern __shared__ float smem[];

    const int b  = blockIdx.z;
    const int h0 = blockIdx.y * TH;
    const int w0 = blockIdx.x * TW;
    const int wg = threadIdx.x;   // 0..3
    const int dy = threadIdx.y;   // 0..8
    const int hz = threadIdx.z;   // 0..7
    const int tid = wg + 4 * dy + 36 * hz;

    const unsigned smem_u = (unsigned)__cvta_generic_to_shared(smem);

    // ---- loader roles ----
    // tid <  192      : x2 loader (16 rows x 12 col4)
    // 192 <= tid <264 : x1 loader (8 rows x 9 col4)
    const bool isX2 = (tid < 192);
    const bool isX1 = (tid >= 192) && (tid < 264);
    int  l_goff = 0, l_soff = 0;
    bool l_valid = false;
    if (isX2) {
        int r  = tid / 12, c4 = tid % 12;
        int gh = h0 - 4 + r;
        int gw = w0 - 8 + c4 * 4;
        l_valid = (gh >= 0) && (gh < H_) && (gw >= 0) && (gw < W_);
        l_goff  = l_valid ? (b * CHW_ + gh * W_ + gw) : 0;
        l_soff  = r * X2W + c4 * 4;
    } else if (isX1) {
        int t  = tid - 192;
        int r  = t / 9, c4 = t % 9;
        int gw = w0 + c4 * 4;
        l_valid = (gw < W_);
        l_goff  = l_valid ? (b * CHW_ + (h0 + r) * W_ + gw) : 0;
        l_soff  = r * X1W + c4 * 4;
    }

    auto issue = [&](int k, int bsel) {
        if (isX2) {
            const float* g = x2 + (size_t)k * CC * HW_ + l_goff;
            unsigned s = smem_u + (unsigned)((bsel * BUFF + S1 + l_soff) * 4);
            #pragma unroll
            for (int c = 0; c < CC; ++c)
                cp16(s + (unsigned)(c * (X2H * X2W * 4)), g + (size_t)c * HW_, l_valid);
        } else if (isX1) {
            const float* g = x1 + (size_t)k * CC * HW_ + l_goff;
            unsigned s = smem_u + (unsigned)((bsel * BUFF + l_soff) * 4);
            #pragma unroll
            for (int c = 0; c < CC; ++c)
                cp16(s + (unsigned)(c * (TH * X1W * 4)), g + (size_t)c * HW_, l_valid);
        }
        asm volatile("cp.async.commit_group;");
    };

    // ---- accumulators ----
    // accE[e][p]: dx=2e   (e=0..4), pixels (2p, 2p+1),   p=0..3
    // accO[o][p]: dx=2o+1 (o=0..3), pixels (2p+1, 2p+2), p=0..3
    ull accE[20], accO[16];
    #pragma unroll
    for (int i = 0; i < 20; ++i) accE[i] = 0ull;
    #pragma unroll
    for (int i = 0; i < 16; ++i) accO[i] = 0ull;

    issue(0, 0);

    const int arow = hz * X1W + wg * 8;
    const int brow = (hz + dy) * X2W + 4 + wg * 8;   // br[j] = x2[W0 - 4 + j]

    #pragma unroll 1
    for (int k = 0; k < NC; ++k) {
        if (k + 1 < NC) issue(k + 1, (k + 1) & 1);
        if (k + 1 < NC) asm volatile("cp.async.wait_group 1;");
        else            asm volatile("cp.async.wait_group 0;");
        __syncthreads();

        const float* s1p = smem + (k & 1) * BUFF;
        const float* s2p = s1p + S1;

        #pragma unroll
        for (int c = 0; c < CC; ++c) {
            const float* ap = s1p + c * (TH * X1W) + arow;
            const float* br = s2p + c * (X2H * X2W) + brow;

            // B: 8 aligned pairs straight from LDS.128 — no repacking
            ulonglong2 b01 = *(const ulonglong2*)(br);
            ulonglong2 b23 = *(const ulonglong2*)(br + 4);
            ulonglong2 b45 = *(const ulonglong2*)(br + 8);
            ulonglong2 b67 = *(const ulonglong2*)(br + 12);
            ull BP[8] = { b01.x, b01.y, b23.x, b23.y,
                          b45.x, b45.y, b67.x, b67.y };

            // A: aligned pairs (free) + 4 shifted pairs (the only packs)
            ulonglong2 av0 = *(const ulonglong2*)(ap);      // (a0,a1) (a2,a3)
            ulonglong2 av1 = *(const ulonglong2*)(ap + 4);  // (a4,a5) (a6,a7)
            float a8 = ap[8];
            ull A[4] = { av0.x, av0.y, av1.x, av1.y };
            ull S[4] = { pk2(hiF(av0.x), loF(av0.y)),   // (a1,a2)
                         pk2(hiF(av0.y), loF(av1.x)),   // (a3,a4)
                         pk2(hiF(av1.x), loF(av1.y)),   // (a5,a6)
                         pk2(hiF(av1.y), a8) };         // (a7,a8)

            // even dx=2e: B offset 2p+2e -> BP[p+e]
            #pragma unroll
            for (int e = 0; e < 5; ++e) {
                fma2(accE[e * 4 + 0], A[0], BP[e + 0]);
                fma2(accE[e * 4 + 1], A[1], BP[e + 1]);
                fma2(accE[e * 4 + 2], A[2], BP[e + 2]);
                fma2(accE[e * 4 + 3], A[3], BP[e + 3]);
            }
            // odd dx=2o+1: shifted pixels, B offset 2p+1+dx -> BP[p+o+1]
            #pragma unroll
            for (int o = 0; o < 4; ++o) {
                fma2(accO[o * 4 + 0], S[0], BP[o + 1]);
                fma2(accO[o * 4 + 1], S[1], BP[o + 2]);
                fma2(accO[o * 4 + 2], S[2], BP[o + 3]);
                fma2(accO[o * 4 + 3], S[3], BP[o + 4]);
            }
        }
        __syncthreads();
    }

    // ---- epilogue: mean over C, LeakyReLU, store ----
    const float inv = 1.0f / 128.0f;
    const int h  = h0 + hz;
    const int wb = w0 + wg * 8;

    // even dx: aligned vector stores at w = wb .. wb+7
    #pragma unroll
    for (int e = 0; e < 5; ++e) {
        const int d = dy * 9 + 2 * e;
        float r[8];
        #pragma unroll
        for (int p = 0; p < 4; ++p) {
            float lo, hi;
            upk2(accE[e * 4 + p], lo, hi);
            r[2 * p]     = leaky(lo * inv);
            r[2 * p + 1] = leaky(hi * inv);
        }
        float4* op = (float4*)(out + (size_t)((b * 81 + d) * H_ + h) * W_ + wb);
        op[0] = make_float4(r[0], r[1], r[2], r[3]);
        op[1] = make_float4(r[4], r[5], r[6], r[7]);
    }
    // odd dx: pixels wb+1 .. wb+8 (scalar stores; w=0 handled by edge kernel)
    #pragma unroll
    for (int o = 0; o < 4; ++o) {
        const int d = dy * 9 + 2 * o + 1;
        float* op = out + (size_t)((b * 81 + d) * H_ + h) * W_;
        #pragma unroll
        for (int p = 0; p < 4; ++p) {
            float lo, hi;
            upk2(accO[o * 4 + p], lo, hi);
            int w_lo = wb + 2 * p + 1;
            int w_hi = wb + 2 * p + 2;
            op[w_lo] = leaky(lo * inv);                 // w_lo <= 254 always
            if (w_hi < W_) op[w_hi] = leaky(hi * inv);  // skip w=256 at right edge
        }
    }
}

// w = 0 column, odd dx only. dx in {1,3} -> x2 col dx-4 < 0 -> zero.
// dx in {5,7} -> dot over channels with x2 cols 1 and 3.
__global__ void edge_kernel(const float* __restrict__ x1,
                            const float* __restrict__ x2,
                            float* __restrict__ out)
{
    int idx = blockIdx.x * blockDim.x + threadIdx.x;   // (b*H + h)*9 + dy
    if (idx >= B_ * H_ * NDY) return;
    int dy = idx % 9;
    int h  = (idx / 9) % H_;
    int b  = idx / (9 * H_);
    int r  = h + dy - 4;

    float acc5 = 0.0f, acc7 = 0.0f;
    if (r >= 0 && r < H_) {
        const float* p1 = x1 + (size_t)b * CHW_ + (size_t)h * W_;
        const float* p2 = x2 + (size_t)b * CHW_ + (size_t)r * W_;
        #pragma unroll 4
        for (int c = 0; c < C_; ++c) {
            float xv = p1[(size_t)c * HW_];
            acc5 += xv * p2[(size_t)c * HW_ + 1];
            acc7 += xv * p2[(size_t)c * HW_ + 3];
        }
    }
    const float inv = 1.0f / 128.0f;
    size_t base = ((size_t)b * 81 + (size_t)dy * 9) * HW_ + (size_t)h * W_;
    out[base + 1 * (size_t)HW_] = 0.0f;
    out[base + 3 * (size_t)HW_] = 0.0f;
    out[base + 5 * (size_t)HW_] = leaky(acc5 * inv);
    out[base + 7 * (size_t)HW_] = leaky(acc7 * inv);
}

extern "C" void kernel_launch(void* const* d_in, const int* in_sizes, int n_in,
                              void* d_out, int out_size)
{
    const float* x1 = (const float*)d_in[0];
    const float* x2 = (const float*)d_in[1];
    float* out = (float*)d_out;

    cudaFuncSetAttribute(corr_kernel,
                         cudaFuncAttributeMaxDynamicSharedMemorySize, SMEM_BYTES);

    dim3 grid(W_ / TW, H_ / TH, B_);   // (8, 16, 8)
    dim3 block(4, NDY, TH);            // 288 threads
    corr_kernel<<<grid, block, SMEM_BYTES>>>(x1, x2, out);

    int edge_threads = B_ * H_ * NDY;  // 9216
    edge_kernel<<<(edge_threads + 255) / 256, 256>>>(x1, x2, out);
}

// round 15
// speedup vs baseline: 1.5249x; 1.5249x over previous
#include <cuda_runtime.h>
#include <cstdint>

// Problem constants
#define H_   128
#define W_   256
#define C_   128
#define B_   8
#define HW_  (H_ * W_)
#define CHW_ (C_ * HW_)

// Tiling
#define TH   8              // output rows per block
#define TW   32             // output cols per block
#define NDY  9              // dy values (threadIdx.y)
#define CC   8              // channels per chunk
#define NC   (C_ / CC)      // 16 chunks
#define X2H  (TH + 8)       // 16 x2 rows in tile
#define X2W  52             // 48 data cols + 4 pad (conflict-free, 16B-aligned rows)
#define S1   (CC * TH * TW)          // x1 tile floats  = 2048
#define S2   (CC * X2H * X2W)        // x2 tile floats  = 6656
#define BUFF (S1 + S2)               // 8704 floats per buffer
#define SMEM_BYTES (2 * BUFF * 4)    // 69632 B (double buffered) -> 2 CTAs/SM
#define NTHREADS 288

typedef unsigned long long ull;

__device__ __forceinline__ ull pk2(float lo, float hi) {
    ull r;
    asm("mov.b64 %0, {%1, %2};"
        : "=l"(r) : "r"(__float_as_uint(lo)), "r"(__float_as_uint(hi)));
    return r;
}
__device__ __forceinline__ void fma2(ull& d, ull a, ull b) {
    // packed f32x2 FMA: d.lo += a.lo*b.lo ; d.hi += a.hi*b.hi
    asm("fma.rn.f32x2 %0, %1, %2, %0;" : "+l"(d) : "l"(a), "l"(b));
}
__device__ __forceinline__ void upk2(ull v, float& lo, float& hi) {
    unsigned l, h;
    asm("mov.b64 {%0, %1}, %2;" : "=r"(l), "=r"(h) : "l"(v));
    lo = __uint_as_float(l); hi = __uint_as_float(h);
}
__device__ __forceinline__ float loF(ull v) { return __uint_as_float((unsigned)v); }
__device__ __forceinline__ float hiF(ull v) { return __uint_as_float((unsigned)(v >> 32)); }
__device__ __forceinline__ void cp16(unsigned sdst, const float* g, bool valid) {
    int sz = valid ? 16 : 0;   // src-size 0 => zero-fill 16B
    asm volatile("cp.async.cg.shared.global [%0], [%1], 16, %2;"
                 :: "r"(sdst), "l"(g), "r"(sz));
}

__global__ void __launch_bounds__(NTHREADS, 2)
corr_kernel(const float* __restrict__ x1, const float* __restrict__ x2,
            float* __restrict__ out)
{
    extern __shared__ float smem[];

    const int b  = blockIdx.z;
    const int h0 = blockIdx.y * TH;
    const int w0 = blockIdx.x * TW;
    const int wg = threadIdx.x;   // 0..3  : group of 8 pixels along w
    const int dy = threadIdx.y;   // 0..8  : vertical displacement index
    const int hz = threadIdx.z;   // 0..7  : row within tile
    const int tid = wg + 4 * dy + 36 * hz;

    const unsigned smem_u = (unsigned)__cvta_generic_to_shared(smem);

    // ---- loader roles (chunk-invariant) ----
    // tid <  192 : x2 loader (16 rows x 12 col4)
    // 192..255   : x1 loader (8 rows x 8 col4)
    const bool isX2 = (tid < 192);
    const bool isX1 = (tid >= 192) && (tid < 256);
    int  l_goff = 0, l_soff = 0;
    bool l_valid = false;
    if (isX2) {
        int r  = tid / 12, c4 = tid % 12;
        int gh = h0 - 4 + r;
        int gw = w0 - 8 + c4 * 4;          // tile starts at w0-8 for 16B alignment
        l_valid = (gh >= 0) && (gh < H_) && (gw >= 0) && (gw < W_);
        l_goff  = l_valid ? (b * CHW_ + gh * W_ + gw) : 0;
        l_soff  = r * X2W + c4 * 4;
    } else if (isX1) {
        int t  = tid - 192;
        int r  = t >> 3, c4 = t & 7;
        l_goff = b * CHW_ + (h0 + r) * W_ + w0 + c4 * 4;
        l_soff = r * TW + c4 * 4;
        l_valid = true;
    }

    auto issue = [&](int k, int bsel) {
        if (isX2) {
            const float* g = x2 + (size_t)k * CC * HW_ + l_goff;
            unsigned s = smem_u + (unsigned)((bsel * BUFF + S1 + l_soff) * 4);
            #pragma unroll
            for (int c = 0; c < CC; ++c)
                cp16(s + (unsigned)(c * (X2H * X2W * 4)), g + (size_t)c * HW_, l_valid);
        } else if (isX1) {
            const float* g = x1 + (size_t)k * CC * HW_ + l_goff;
            unsigned s = smem_u + (unsigned)((bsel * BUFF + l_soff) * 4);
            #pragma unroll
            for (int c = 0; c < CC; ++c)
                cp16(s + (unsigned)(c * (TH * TW * 4)), g + (size_t)c * HW_, true);
        }
        asm volatile("cp.async.commit_group;");
    };

    // ---- accumulators: acc[dx*4+p] covers pixels (2p, 2p+1) ----
    ull acc[36];
    #pragma unroll
    for (int i = 0; i < 36; ++i) acc[i] = 0ull;

    issue(0, 0);

    const int arow = hz * TW + wg * 8;
    const int brow = (hz + dy) * X2W + 4 + wg * 8;   // br[j] = x2[w0 - 4 + j]

    #pragma unroll 1
    for (int k = 0; k < NC; ++k) {
        if (k + 1 < NC) issue(k + 1, (k + 1) & 1);
        if (k + 1 < NC) asm volatile("cp.async.wait_group 1;");
        else            asm volatile("cp.async.wait_group 0;");
        __syncthreads();

        const float* s1p = smem + (k & 1) * BUFF;
        const float* s2p = s1p + S1;

        #pragma unroll
        for (int c = 0; c < CC; ++c) {
            const float* ap = s1p + c * (TH * TW) + arow;
            const float* br = s2p + c * (X2H * X2W) + brow;

            // A: 4 aligned pairs straight from LDS.128 — zero repacking
            ulonglong2 av0 = *(const ulonglong2*)(ap);
            ulonglong2 av1 = *(const ulonglong2*)(ap + 4);
            ull A[4] = { av0.x, av0.y, av1.x, av1.y };

            // B: 8 aligned (even-offset) pairs straight from LDS.128
            ulonglong2 b01 = *(const ulonglong2*)(br);
            ulonglong2 b23 = *(const ulonglong2*)(br + 4);
            ulonglong2 b45 = *(const ulonglong2*)(br + 8);
            ulonglong2 b67 = *(const ulonglong2*)(br + 12);
            ull BPe[8] = { b01.x, b01.y, b23.x, b23.y,
                           b45.x, b45.y, b67.x, b67.y };

            // even dx first: operands ready right after the loads
            // B pair offset 2p+dx (even) -> BPe[p + dx/2]
            #pragma unroll
            for (int e = 0; e < 5; ++e) {   // dx = 2e
                fma2(acc[(2 * e) * 4 + 0], A[0], BPe[e + 0]);
                fma2(acc[(2 * e) * 4 + 1], A[1], BPe[e + 1]);
                fma2(acc[(2 * e) * 4 + 2], A[2], BPe[e + 2]);
                fma2(acc[(2 * e) * 4 + 3], A[3], BPe[e + 3]);
            }

            // odd-offset B pairs: the only packs (7 per channel)
            ull BO[7];
            #pragma unroll
            for (int j = 0; j < 7; ++j)
                BO[j] = pk2(hiF(BPe[j]), loF(BPe[j + 1]));   // (b[2j+1], b[2j+2])

            // odd dx: B pair offset 2p+dx (odd) -> BO[p + (dx-1)/2]
            #pragma unroll
            for (int o = 0; o < 4; ++o) {   // dx = 2o+1
                fma2(acc[(2 * o + 1) * 4 + 0], A[0], BO[o + 0]);
                fma2(acc[(2 * o + 1) * 4 + 1], A[1], BO[o + 1]);
                fma2(acc[(2 * o + 1) * 4 + 2], A[2], BO[o + 2]);
                fma2(acc[(2 * o + 1) * 4 + 3], A[3], BO[o + 3]);
            }
        }
        __syncthreads();
    }

    // ---- epilogue: mean over C, LeakyReLU(0.1), aligned float4 stores ----
    const float inv = 1.0f / 128.0f;
    const int h  = h0 + hz;
    const int wb = w0 + wg * 8;
    #pragma unroll
    for (int dx = 0; dx < 9; ++dx) {
        const int d = dy * 9 + dx;
        float r[8];
        #pragma unroll
        for (int p = 0; p < 4; ++p) {
            float lo, hi;
            upk2(acc[dx * 4 + p], lo, hi);
            lo *= inv; hi *= inv;
            r[2 * p]     = (lo > 0.0f) ? lo : 0.1f * lo;
            r[2 * p + 1] = (hi > 0.0f) ? hi : 0.1f * hi;
        }
        float4* op = (float4*)(out + (size_t)((b * 81 + d) * H_ + h) * W_ + wb);
        op[0] = make_float4(r[0], r[1], r[2], r[3]);
        op[1] = make_float4(r[4], r[5], r[6], r[7]);
    }
}

extern "C" void kernel_launch(void* const* d_in, const int* in_sizes, int n_in,
                              void* d_out, int out_size)
{
    const float* x1 = (const float*)d_in[0];
    const float* x2 = (const float*)d_in[1];
    float* out = (float*)d_out;

    cudaFuncSetAttribute(corr_kernel,
                         cudaFuncAttributeMaxDynamicSharedMemorySize, SMEM_BYTES);

    dim3 grid(W_ / TW, H_ / TH, B_);   // (8, 16, 8) = 1024 blocks
    dim3 block(4, NDY, TH);            // 288 threads
    corr_kernel<<<grid, block, SMEM_BYTES>>>(x1, x2, out);
}